// round 4
// baseline (speedup 1.0000x reference)
#include <cuda_runtime.h>
#include <math.h>

#define BATCH 8
#define C_IN 256
#define C_INT 128
#define NSP 4096   // H*W = 64*64
#define MSP 1024   // pooled spatial = 32*32
#define NPIX 32768 // BATCH*NSP

// ---------------- scratch (static device arrays; no allocation) ----------------
__device__ float d_theta[BATCH * C_INT * NSP];   // [B][Ci][N]   16 MB
__device__ float d_phi  [BATCH * C_INT * MSP];   // [B][Ci][M]    4 MB
__device__ float d_g    [BATCH * MSP * C_INT];   // [B][M][Ci]    4 MB
__device__ float d_y    [BATCH * NSP * C_INT];   // [B][N][Ci]   16 MB
__device__ float d_Wy   [BATCH * C_IN * NSP];    // [B][C][N]    32 MB
__device__ float d_wpack[384 * C_IN];
__device__ float d_bpack[384];
__device__ float d_sum  [C_IN];
__device__ float d_sumsq[C_IN];

// ---------------- pack theta/phi/g weights into one [384,256] matrix ----------------
__global__ void pack_kernel(const float* __restrict__ tw, const float* __restrict__ tb,
                            const float* __restrict__ pw, const float* __restrict__ pb,
                            const float* __restrict__ gw, const float* __restrict__ gb) {
    int row = blockIdx.x;          // 0..383
    int t = threadIdx.x;           // 0..255
    const float* w; const float* bs; int r;
    if (row < 128)      { w = tw; bs = tb; r = row; }
    else if (row < 256) { w = pw; bs = pb; r = row - 128; }
    else                { w = gw; bs = gb; r = row - 256; }
    d_wpack[row * 256 + t] = w[r * 256 + t];
    if (t == 0) d_bpack[row] = bs[r];
}

// ---------------- fused theta/phi/g conv (GEMM 384x4096, K=256) + maxpool epilogue ----
// grid (32, 6, 8): bx = 128-wide spatial tile (== 2 image rows), by = 64-row channel tile
__global__ __launch_bounds__(256) void conv3_kernel(const float* __restrict__ x) {
    __shared__ __align__(16) float sbuf[8192];   // 32 KB; reused for pooling epilogue
    float* As = sbuf;          // [16][64]
    float* Bs = sbuf + 1024;   // [16][128]

    int b  = blockIdx.z;
    int by = blockIdx.y;       // 0..5
    int bx = blockIdx.x;       // 0..31
    int row0 = by * 64;
    int n0   = bx * 128;
    int tid = threadIdx.x;
    int ty = tid >> 5;         // 0..7
    int tx = tid & 31;         // 0..31

    float acc[8][4];
#pragma unroll
    for (int i = 0; i < 8; i++)
#pragma unroll
        for (int j = 0; j < 4; j++) acc[i][j] = 0.f;

    const float* xb = x + (size_t)b * C_IN * NSP;
    int a_r = tid >> 2;            // 0..63
    int a_k = (tid & 3) * 4;       // 0,4,8,12
    int b_k = tid >> 5;            // 0..7
    int b_n = (tid & 31) * 4;

    for (int k0 = 0; k0 < 256; k0 += 16) {
        float4 av = *(const float4*)&d_wpack[(row0 + a_r) * 256 + k0 + a_k];
        As[(a_k + 0) * 64 + a_r] = av.x;
        As[(a_k + 1) * 64 + a_r] = av.y;
        As[(a_k + 2) * 64 + a_r] = av.z;
        As[(a_k + 3) * 64 + a_r] = av.w;
#pragma unroll
        for (int h = 0; h < 2; h++) {
            int kk = b_k + h * 8;
            *(float4*)&Bs[kk * 128 + b_n] =
                *(const float4*)&xb[(size_t)(k0 + kk) * NSP + n0 + b_n];
        }
        __syncthreads();
#pragma unroll
        for (int kk = 0; kk < 16; kk++) {
            float4 a01 = *(const float4*)&As[kk * 64 + ty * 8];
            float4 a23 = *(const float4*)&As[kk * 64 + ty * 8 + 4];
            float a[8] = {a01.x, a01.y, a01.z, a01.w, a23.x, a23.y, a23.z, a23.w};
            float4 bv = *(const float4*)&Bs[kk * 128 + tx * 4];
#pragma unroll
            for (int i = 0; i < 8; i++) {
                acc[i][0] += a[i] * bv.x;
                acc[i][1] += a[i] * bv.y;
                acc[i][2] += a[i] * bv.z;
                acc[i][3] += a[i] * bv.w;
            }
        }
        __syncthreads();
    }

#pragma unroll
    for (int i = 0; i < 8; i++) {
        float bb = d_bpack[row0 + ty * 8 + i];
#pragma unroll
        for (int j = 0; j < 4; j++) acc[i][j] += bb;
    }

    if (by < 2) {
        // theta rows -> write [B][Ci][N]
#pragma unroll
        for (int i = 0; i < 8; i++) {
            int ci = row0 + ty * 8 + i;
            float4 v = make_float4(acc[i][0], acc[i][1], acc[i][2], acc[i][3]);
            *(float4*)&d_theta[((size_t)b * C_INT + ci) * NSP + n0 + tx * 4] = v;
        }
    } else {
        // stage full 64x128 tile to smem, then 2x2 maxpool (tile == 2 image rows)
        float* Ps = sbuf;
        __syncthreads();
#pragma unroll
        for (int i = 0; i < 8; i++)
            *(float4*)&Ps[(ty * 8 + i) * 128 + tx * 4] =
                make_float4(acc[i][0], acc[i][1], acc[i][2], acc[i][3]);
        __syncthreads();
        int isphi  = (by < 4);
        int cibase = isphi ? (by - 2) * 64 : (by - 4) * 64;
#pragma unroll
        for (int it = 0; it < 8; it++) {
            int idx = tid + it * 256;     // 0..2047
            int cil = idx >> 5;           // 0..63
            int wq  = idx & 31;           // 0..31
            float v0 = Ps[cil * 128 + wq * 2];
            float v1 = Ps[cil * 128 + wq * 2 + 1];
            float v2 = Ps[cil * 128 + 64 + wq * 2];
            float v3 = Ps[cil * 128 + 64 + wq * 2 + 1];
            float v = fmaxf(fmaxf(v0, v1), fmaxf(v2, v3));
            int m  = bx * 32 + wq;
            int ci = cibase + cil;
            if (isphi) d_phi[((size_t)b * C_INT + ci) * MSP + m] = v;
            else       d_g  [((size_t)b * MSP + m) * C_INT + ci] = v;
        }
    }
}

// ---------------- fused attention, ONLINE softmax (flash-style) ----------------------
// grid (128, 8), 512 threads; block = 32 n-rows. f slab never materialized.
// dyn smem: theta 16384 + chunk 65536 + f_ch 16384 + stats 384 = 98688 B (2 blocks/SM)
#define ATTN_SMEM 98688
__global__ __launch_bounds__(512) void attn_kernel() {
    extern __shared__ __align__(16) float sm[];
    float* th_s = sm;                    // [128 ci][32 r]     16 KB
    float* ch_s = sm + 4096;             // [128][128]         64 KB (phi chunk, then g chunk)
    float* f_ch = sm + 4096 + 16384;     // [32 r][128 m]      16 KB
    float* m_s  = f_ch + 4096;           // [32] running max
    float* l_s  = m_s + 32;              // [32] running sum
    float* al_s = l_s + 32;              // [32] rescale alpha

    int b  = blockIdx.y;
    int n0 = blockIdx.x * 32;
    int tid = threadIdx.x;
    int lane = tid & 31;
    int wrp  = tid >> 5;                 // 0..15
    int frow = (tid >> 6) * 4;           // 0,4,...,28 (constant within a warp)
    int fcol = (tid & 63) * 2;           // 0..126

    // load theta tile -> th_s[ci*32 + r]
#pragma unroll
    for (int it = 0; it < 2; it++) {
        int l  = tid + it * 512;             // 0..1023 (float4 units)
        int ci = l >> 3;
        int r4 = (l & 7) * 4;
        *(float4*)&th_s[ci * 32 + r4] =
            *(const float4*)&d_theta[((size_t)b * C_INT + ci) * NSP + n0 + r4];
    }
    if (tid < 32) { m_s[tid] = -1e30f; l_s[tid] = 0.f; }
    __syncthreads();

    float yac[4][2];
#pragma unroll
    for (int i = 0; i < 4; i++) { yac[i][0] = 0.f; yac[i][1] = 0.f; }

    const float* phib = &d_phi[(size_t)b * C_INT * MSP];

    for (int mc = 0; mc < 8; mc++) {
        int mbase = mc * 128;
        // ---- load phi chunk [128 k][128 m] ----
#pragma unroll
        for (int it = 0; it < 8; it++) {
            int lin = tid + it * 512;          // float4 index 0..4095
            int kk = lin >> 5;
            int mq = (lin & 31) * 4;
            *(float4*)&ch_s[kk * 128 + mq] =
                *(const float4*)&phib[(size_t)kk * MSP + mbase + mq];
        }
        __syncthreads();

        // ---- f_ch[32][128] = theta^T @ phi_chunk ----
        float a4[4][2];
#pragma unroll
        for (int i = 0; i < 4; i++) { a4[i][0] = 0.f; a4[i][1] = 0.f; }
#pragma unroll 8
        for (int kk = 0; kk < 128; kk++) {
            float4 av = *(const float4*)&th_s[kk * 32 + frow];   // warp-broadcast
            float2 bv = *(const float2*)&ch_s[kk * 128 + fcol];
            a4[0][0] += av.x * bv.x;  a4[0][1] += av.x * bv.y;
            a4[1][0] += av.y * bv.x;  a4[1][1] += av.y * bv.y;
            a4[2][0] += av.z * bv.x;  a4[2][1] += av.z * bv.y;
            a4[3][0] += av.w * bv.x;  a4[3][1] += av.w * bv.y;
        }
#pragma unroll
        for (int i = 0; i < 4; i++)
            *(float2*)&f_ch[(frow + i) * 128 + fcol] = make_float2(a4[i][0], a4[i][1]);
        __syncthreads();

        // ---- online softmax update; warp wrp owns rows 2wrp, 2wrp+1 ----
#pragma unroll
        for (int q = 0; q < 2; q++) {
            int row = wrp * 2 + q;
            float* fr = &f_ch[row * 128];
            float mx = -1e30f;
#pragma unroll
            for (int it = 0; it < 4; it++) mx = fmaxf(mx, fr[lane + it * 32]);
#pragma unroll
            for (int o = 16; o; o >>= 1) mx = fmaxf(mx, __shfl_xor_sync(0xffffffffu, mx, o));
            float mold = m_s[row];
            float mnew = fmaxf(mold, mx);
            float s = 0.f;
#pragma unroll
            for (int it = 0; it < 4; it++) {
                float e = expf(fr[lane + it * 32] - mnew);
                fr[lane + it * 32] = e;
                s += e;
            }
#pragma unroll
            for (int o = 16; o; o >>= 1) s += __shfl_xor_sync(0xffffffffu, s, o);
            if (lane == 0) {
                float alpha = expf(mold - mnew);    // 0 on first chunk
                al_s[row] = alpha;
                l_s[row]  = l_s[row] * alpha + s;
                m_s[row]  = mnew;
            }
        }
        // ---- load g chunk [128 m][128 c] into ch_s (phi no longer needed) ----
        {
            const float4* gsrc = (const float4*)&d_g[((size_t)b * MSP + mbase) * C_INT];
#pragma unroll
            for (int it = 0; it < 8; it++) {
                int l4 = tid + it * 512;
                ((float4*)ch_s)[l4] = gsrc[l4];
            }
        }
        __syncthreads();

        // ---- y accumulate: y = y*alpha + exp(f) @ g_chunk ----
#pragma unroll
        for (int i = 0; i < 4; i++) {
            float a = al_s[frow + i];
            yac[i][0] *= a; yac[i][1] *= a;
        }
#pragma unroll 8
        for (int mm = 0; mm < 128; mm++) {
            float a[4];
#pragma unroll
            for (int i = 0; i < 4; i++) a[i] = f_ch[(frow + i) * 128 + mm];
            float2 bv = *(const float2*)&ch_s[mm * 128 + fcol];
#pragma unroll
            for (int i = 0; i < 4; i++) {
                yac[i][0] += a[i] * bv.x;
                yac[i][1] += a[i] * bv.y;
            }
        }
        __syncthreads();
    }

    // ---- finalize: divide by running sum, write y [B][N][Ci] ----
#pragma unroll
    for (int i = 0; i < 4; i++) {
        float inv = 1.f / l_s[frow + i];
        *(float2*)&d_y[((size_t)b * NSP + n0 + frow + i) * C_INT + fcol] =
            make_float2(yac[i][0] * inv, yac[i][1] * inv);
    }
}

// ---------------- zero BN stats ----------------
__global__ void zero_stats_kernel() {
    int t = threadIdx.x;
    if (t < 256) { d_sum[t] = 0.f; d_sumsq[t] = 0.f; }
}

// ---------------- W conv (GEMM 256x4096, K=128) + per-channel sum/sumsq --------------
__global__ __launch_bounds__(256) void wconv_kernel(const float* __restrict__ Ww,
                                                    const float* __restrict__ Wb) {
    __shared__ __align__(16) float As[16 * 64];
    __shared__ __align__(16) float Bs[16 * 128];
    int b  = blockIdx.z;
    int by = blockIdx.y;        // 0..3
    int bx = blockIdx.x;        // 0..31
    int c0 = by * 64;
    int n0 = bx * 128;
    int tid = threadIdx.x;
    int ty = tid >> 5;
    int tx = tid & 31;

    float acc[8][4];
#pragma unroll
    for (int i = 0; i < 8; i++)
#pragma unroll
        for (int j = 0; j < 4; j++) acc[i][j] = 0.f;

    int a_r = tid >> 2, a_k = (tid & 3) * 4;
    int b_n = tid >> 1, b_kq = (tid & 1) * 8;
    const float* yb = d_y + (size_t)b * NSP * C_INT;

    for (int k0 = 0; k0 < 128; k0 += 16) {
        float4 av = *(const float4*)&Ww[(c0 + a_r) * 128 + k0 + a_k];
        As[(a_k + 0) * 64 + a_r] = av.x;
        As[(a_k + 1) * 64 + a_r] = av.y;
        As[(a_k + 2) * 64 + a_r] = av.z;
        As[(a_k + 3) * 64 + a_r] = av.w;
#pragma unroll
        for (int h = 0; h < 2; h++) {
            float4 bv = *(const float4*)&yb[(size_t)(n0 + b_n) * C_INT + k0 + b_kq + h * 4];
            Bs[(b_kq + h * 4 + 0) * 128 + b_n] = bv.x;
            Bs[(b_kq + h * 4 + 1) * 128 + b_n] = bv.y;
            Bs[(b_kq + h * 4 + 2) * 128 + b_n] = bv.z;
            Bs[(b_kq + h * 4 + 3) * 128 + b_n] = bv.w;
        }
        __syncthreads();
#pragma unroll
        for (int kk = 0; kk < 16; kk++) {
            float4 a01 = *(const float4*)&As[kk * 64 + ty * 8];
            float4 a23 = *(const float4*)&As[kk * 64 + ty * 8 + 4];
            float a[8] = {a01.x, a01.y, a01.z, a01.w, a23.x, a23.y, a23.z, a23.w};
            float4 bv = *(const float4*)&Bs[kk * 128 + tx * 4];
#pragma unroll
            for (int i = 0; i < 8; i++) {
                acc[i][0] += a[i] * bv.x;
                acc[i][1] += a[i] * bv.y;
                acc[i][2] += a[i] * bv.z;
                acc[i][3] += a[i] * bv.w;
            }
        }
        __syncthreads();
    }

#pragma unroll
    for (int i = 0; i < 8; i++) {
        float bb = Wb[c0 + ty * 8 + i];
#pragma unroll
        for (int j = 0; j < 4; j++) acc[i][j] += bb;
        *(float4*)&d_Wy[((size_t)b * C_IN + c0 + ty * 8 + i) * NSP + n0 + tx * 4] =
            make_float4(acc[i][0], acc[i][1], acc[i][2], acc[i][3]);
    }

    // per-channel partial sums across this tile's 128 n values
#pragma unroll
    for (int i = 0; i < 8; i++) {
        float s = acc[i][0] + acc[i][1] + acc[i][2] + acc[i][3];
        float q = acc[i][0] * acc[i][0] + acc[i][1] * acc[i][1]
                + acc[i][2] * acc[i][2] + acc[i][3] * acc[i][3];
#pragma unroll
        for (int o = 16; o; o >>= 1) {
            s += __shfl_xor_sync(0xffffffffu, s, o);
            q += __shfl_xor_sync(0xffffffffu, q, o);
        }
        if (tx == 0) {
            atomicAdd(&d_sum[c0 + ty * 8 + i], s);
            atomicAdd(&d_sumsq[c0 + ty * 8 + i], q);
        }
    }
}

// ---------------- BN (training stats) + residual ----------------
__global__ __launch_bounds__(256) void finalize_kernel(const float* __restrict__ x,
                                                       const float* __restrict__ gamma,
                                                       const float* __restrict__ beta,
                                                       float* __restrict__ out) {
    size_t i4  = (size_t)blockIdx.x * 256 + threadIdx.x;
    size_t idx = i4 * 4;
    int c = (int)((idx >> 12) & 255);
    float mean = d_sum[c] * (1.f / (float)NPIX);
    float var  = d_sumsq[c] * (1.f / (float)NPIX) - mean * mean;
    float inv  = 1.f / sqrtf(fmaxf(var, 0.f) + 1e-5f);
    float ga = gamma[c] * inv;
    float be = beta[c] - mean * ga;
    float4 w  = *(const float4*)&d_Wy[idx];
    float4 xv = *(const float4*)&x[idx];
    float4 o;
    o.x = w.x * ga + be + xv.x;
    o.y = w.y * ga + be + xv.y;
    o.z = w.z * ga + be + xv.z;
    o.w = w.w * ga + be + xv.w;
    *(float4*)&out[idx] = o;
}

// ---------------- launcher ----------------
extern "C" void kernel_launch(void* const* d_in, const int* in_sizes, int n_in,
                              void* d_out, int out_size) {
    const float* x       = (const float*)d_in[0];
    const float* theta_w = (const float*)d_in[1];
    const float* theta_b = (const float*)d_in[2];
    const float* phi_w   = (const float*)d_in[3];
    const float* phi_b   = (const float*)d_in[4];
    const float* g_w     = (const float*)d_in[5];
    const float* g_b     = (const float*)d_in[6];
    const float* W_w     = (const float*)d_in[7];
    const float* W_b     = (const float*)d_in[8];
    const float* bn_g    = (const float*)d_in[9];
    const float* bn_b    = (const float*)d_in[10];
    float* out = (float*)d_out;

    cudaFuncSetAttribute(attn_kernel, cudaFuncAttributeMaxDynamicSharedMemorySize, ATTN_SMEM);

    pack_kernel<<<384, 256>>>(theta_w, theta_b, phi_w, phi_b, g_w, g_b);
    conv3_kernel<<<dim3(32, 6, BATCH), 256>>>(x);
    attn_kernel<<<dim3(128, BATCH), 512, ATTN_SMEM>>>();
    zero_stats_kernel<<<1, 256>>>();
    wconv_kernel<<<dim3(32, 4, BATCH), 256>>>(W_w, W_b);
    finalize_kernel<<<8192, 256>>>(x, bn_g, bn_b, out);
}

// round 9
// speedup vs baseline: 1.7090x; 1.7090x over previous
#include <cuda_runtime.h>
#include <cuda_bf16.h>
#include <stdint.h>
#include <cstdint>
#include <math.h>

#define BATCH 8
#define C_IN 256
#define C_INT 128
#define NSP 4096   // H*W = 64*64
#define MSP 1024   // pooled spatial = 32*32
#define NPIX 32768 // BATCH*NSP

// ---------------- scratch (static device arrays; no allocation) ----------------
__device__ float d_theta[BATCH * C_INT * NSP];   // [B][Ci][N]   16 MB
__device__ float d_phi  [BATCH * MSP * C_INT];   // [B][M][Ci]    4 MB  (row m, k=ci contiguous)
__device__ float d_g    [BATCH * C_INT * MSP];   // [B][Ci][M]    4 MB  (row c, k=m contiguous)
__device__ float d_y    [BATCH * NSP * C_INT];   // [B][N][Ci]   16 MB
__device__ float d_Wy   [BATCH * C_IN * NSP];    // [B][C][N]    32 MB
__device__ float d_wpack[384 * C_IN];
__device__ float d_bpack[384];
__device__ float d_sum  [C_IN];
__device__ float d_sumsq[C_IN];

// ======================= warp-MMA helpers (sm_80+, safe on sm_103) =======================
__device__ __forceinline__ uint32_t smem_u32(const void* p) {
    uint32_t a;
    asm("{ .reg .u64 t; cvta.to.shared.u64 t, %1; cvt.u32.u64 %0, t; }" : "=r"(a) : "l"(p));
    return a;
}
__device__ __forceinline__ void ldsm4(uint32_t* r, uint32_t addr) {
    asm volatile("ldmatrix.sync.aligned.m8n8.x4.shared.b16 {%0,%1,%2,%3}, [%4];"
        : "=r"(r[0]), "=r"(r[1]), "=r"(r[2]), "=r"(r[3]) : "r"(addr));
}
__device__ __forceinline__ void mma_bf16(float* c, const uint32_t* a, uint32_t b0, uint32_t b1) {
    asm volatile("mma.sync.aligned.m16n8k16.row.col.f32.bf16.bf16.f32 "
        "{%0,%1,%2,%3}, {%4,%5,%6,%7}, {%8,%9}, {%0,%1,%2,%3};"
        : "+f"(c[0]), "+f"(c[1]), "+f"(c[2]), "+f"(c[3])
        : "r"(a[0]), "r"(a[1]), "r"(a[2]), "r"(a[3]), "r"(b0), "r"(b1));
}
// split fp32 pair (even, odd col) into packed bf16x2 hi + lo(residual); lo half = even col
__device__ __forceinline__ void split2(float v0, float v1, uint32_t& hi, uint32_t& lo) {
    __nv_bfloat16 h0 = __float2bfloat16(v0), h1 = __float2bfloat16(v1);
    float r0 = v0 - __bfloat162float(h0), r1 = v1 - __bfloat162float(h1);
    __nv_bfloat16 l0 = __float2bfloat16(r0), l1 = __float2bfloat16(r1);
    hi = (uint32_t)__bfloat16_as_ushort(h0) | ((uint32_t)__bfloat16_as_ushort(h1) << 16);
    lo = (uint32_t)__bfloat16_as_ushort(l0) | ((uint32_t)__bfloat16_as_ushort(l1) << 16);
}

// SMEM layout: bf16 tiles, 128 rows x 128 cols, row pitch 136 bf16 (= 272 B)
#define SPITCH 136
#define TH_HI 0
#define TH_LO 34816
#define CH_HI 69632
#define CH_LO 104448
#define ATTN_SMEM 139264

// ---------------- pack theta/phi/g weights into one [384,256] matrix ----------------
__global__ void pack_kernel(const float* __restrict__ tw, const float* __restrict__ tb,
                            const float* __restrict__ pw, const float* __restrict__ pb,
                            const float* __restrict__ gw, const float* __restrict__ gb) {
    int row = blockIdx.x;
    int t = threadIdx.x;
    const float* w; const float* bs; int r;
    if (row < 128)      { w = tw; bs = tb; r = row; }
    else if (row < 256) { w = pw; bs = pb; r = row - 128; }
    else                { w = gw; bs = gb; r = row - 256; }
    d_wpack[row * 256 + t] = w[r * 256 + t];
    if (t == 0) d_bpack[row] = bs[r];
}

// ---------------- fused theta/phi/g conv (GEMM 384x4096, K=256) + maxpool epilogue ----
__global__ __launch_bounds__(256) void conv3_kernel(const float* __restrict__ x) {
    __shared__ __align__(16) float sbuf[8192];
    float* As = sbuf;
    float* Bs = sbuf + 1024;

    int b  = blockIdx.z;
    int by = blockIdx.y;       // 0..5
    int bx = blockIdx.x;       // 0..31
    int row0 = by * 64;
    int n0   = bx * 128;
    int tid = threadIdx.x;
    int ty = tid >> 5;
    int tx = tid & 31;

    float acc[8][4];
#pragma unroll
    for (int i = 0; i < 8; i++)
#pragma unroll
        for (int j = 0; j < 4; j++) acc[i][j] = 0.f;

    const float* xb = x + (size_t)b * C_IN * NSP;
    int a_r = tid >> 2;
    int a_k = (tid & 3) * 4;
    int b_k = tid >> 5;
    int b_n = (tid & 31) * 4;

    for (int k0 = 0; k0 < 256; k0 += 16) {
        float4 av = *(const float4*)&d_wpack[(row0 + a_r) * 256 + k0 + a_k];
        As[(a_k + 0) * 64 + a_r] = av.x;
        As[(a_k + 1) * 64 + a_r] = av.y;
        As[(a_k + 2) * 64 + a_r] = av.z;
        As[(a_k + 3) * 64 + a_r] = av.w;
#pragma unroll
        for (int h = 0; h < 2; h++) {
            int kk = b_k + h * 8;
            *(float4*)&Bs[kk * 128 + b_n] =
                *(const float4*)&xb[(size_t)(k0 + kk) * NSP + n0 + b_n];
        }
        __syncthreads();
#pragma unroll
        for (int kk = 0; kk < 16; kk++) {
            float4 a01 = *(const float4*)&As[kk * 64 + ty * 8];
            float4 a23 = *(const float4*)&As[kk * 64 + ty * 8 + 4];
            float a[8] = {a01.x, a01.y, a01.z, a01.w, a23.x, a23.y, a23.z, a23.w};
            float4 bv = *(const float4*)&Bs[kk * 128 + tx * 4];
#pragma unroll
            for (int i = 0; i < 8; i++) {
                acc[i][0] += a[i] * bv.x;
                acc[i][1] += a[i] * bv.y;
                acc[i][2] += a[i] * bv.z;
                acc[i][3] += a[i] * bv.w;
            }
        }
        __syncthreads();
    }

#pragma unroll
    for (int i = 0; i < 8; i++) {
        float bb = d_bpack[row0 + ty * 8 + i];
#pragma unroll
        for (int j = 0; j < 4; j++) acc[i][j] += bb;
    }

    if (by < 2) {
#pragma unroll
        for (int i = 0; i < 8; i++) {
            int ci = row0 + ty * 8 + i;
            float4 v = make_float4(acc[i][0], acc[i][1], acc[i][2], acc[i][3]);
            *(float4*)&d_theta[((size_t)b * C_INT + ci) * NSP + n0 + tx * 4] = v;
        }
    } else {
        float* Ps = sbuf;
        __syncthreads();
#pragma unroll
        for (int i = 0; i < 8; i++)
            *(float4*)&Ps[(ty * 8 + i) * 128 + tx * 4] =
                make_float4(acc[i][0], acc[i][1], acc[i][2], acc[i][3]);
        __syncthreads();
        int isphi  = (by < 4);
        int cibase = isphi ? (by - 2) * 64 : (by - 4) * 64;
#pragma unroll
        for (int it = 0; it < 8; it++) {
            int idx = tid + it * 256;
            int cil = idx >> 5;
            int wq  = idx & 31;
            float v0 = Ps[cil * 128 + wq * 2];
            float v1 = Ps[cil * 128 + wq * 2 + 1];
            float v2 = Ps[cil * 128 + 64 + wq * 2];
            float v3 = Ps[cil * 128 + 64 + wq * 2 + 1];
            float v = fmaxf(fmaxf(v0, v1), fmaxf(v2, v3));
            int m  = bx * 32 + wq;
            int ci = cibase + cil;
            if (isphi) d_phi[((size_t)b * MSP + m) * C_INT + ci] = v;   // [B][M][Ci]
            else       d_g  [((size_t)b * C_INT + ci) * MSP + m] = v;   // [B][Ci][M]
        }
    }
}

// ---------------- attention via mma.sync bf16x3 (flash, P kept in registers) ----------
// grid (32, 8), 256 threads (8 warps); block = 128 n-rows. Warp w owns rows 16w..16w+15.
__global__ __launch_bounds__(256, 1) void attn_tc_kernel() {
    extern __shared__ __align__(16) char smem[];
    uint32_t sb = smem_u32(smem);
    int tid  = threadIdx.x;
    int wid  = tid >> 5;
    int lane = tid & 31;
    int b  = blockIdx.y;
    int n0 = blockIdx.x * 128;
    int wn0 = wid * 16;                      // warp's first n-row (local)
    int g   = lane >> 2;                     // groupID 0..7
    int tig = lane & 3;                      // thread in group

    // ldmatrix lane offsets (bytes)
    int within = lane & 7, sub = lane >> 3;
    uint32_t a_loff = (uint32_t)((wn0 + (sub & 1) * 8 + within) * (SPITCH * 2) + (sub >> 1) * 16);
    uint32_t b_loff = (uint32_t)(((sub >> 1) * 8 + within) * (SPITCH * 2) + (sub & 1) * 16);

    // ---- stage theta tile [n][k=ci] split hi/lo into smem (coalesced global reads) ----
    {
        const float* tp = d_theta + (size_t)b * C_INT * NSP + n0;
        for (int it = 0; it < 32; it++) {
            int lin = tid + it * 256;          // 0..8191 over (ci, n-pair)
            int ci  = lin >> 6;                // 0..127
            int n2  = (lin & 63) * 2;          // 0..126
            float v0 = tp[(size_t)ci * NSP + n2];
            float v1 = tp[(size_t)ci * NSP + n2 + 1];
            __nv_bfloat16 h0 = __float2bfloat16(v0), h1 = __float2bfloat16(v1);
            float r0 = v0 - __bfloat162float(h0), r1 = v1 - __bfloat162float(h1);
            __nv_bfloat16* th = (__nv_bfloat16*)(smem + TH_HI);
            __nv_bfloat16* tl = (__nv_bfloat16*)(smem + TH_LO);
            th[n2 * SPITCH + ci] = h0;
            th[(n2 + 1) * SPITCH + ci] = h1;
            tl[n2 * SPITCH + ci] = __float2bfloat16(r0);
            tl[(n2 + 1) * SPITCH + ci] = __float2bfloat16(r1);
        }
    }
    __syncthreads();

    float ya[16][4];
#pragma unroll
    for (int t = 0; t < 16; t++)
#pragma unroll
        for (int j = 0; j < 4; j++) ya[t][j] = 0.f;
    float s0 = 0.f, s1 = 0.f;   // row sums for rows g and g+8

    for (int mc = 0; mc < 8; mc++) {
        int m0 = mc * 128;
        // ---- load phi chunk [m][k=ci] split -> CH ----
        {
            const float* src = d_phi + ((size_t)b * MSP + m0) * C_INT;
            for (int it = 0; it < 32; it++) {
                int lin = tid + it * 256;            // float2 idx 0..8191
                int row = lin >> 6;
                int c2  = (lin & 63) * 2;
                float2 v = *(const float2*)(src + (size_t)row * C_INT + c2);
                uint32_t hi, lo; split2(v.x, v.y, hi, lo);
                uint32_t off = (uint32_t)(row * (SPITCH * 2) + c2 * 2);
                *(uint32_t*)(smem + CH_HI + off) = hi;
                *(uint32_t*)(smem + CH_LO + off) = lo;
            }
        }
        __syncthreads();

        // ---- MMA1: f[16 x 128] = theta x phi^T (bf16x3) ----
        float fa[16][4];
#pragma unroll
        for (int t = 0; t < 16; t++)
#pragma unroll
            for (int j = 0; j < 4; j++) fa[t][j] = 0.f;
#pragma unroll
        for (int k8 = 0; k8 < 8; k8++) {
            uint32_t ka = (uint32_t)(k8 * 32);   // k byte offset (16 bf16)
            uint32_t ah[4], al[4];
            ldsm4(ah, sb + TH_HI + a_loff + ka);
            ldsm4(al, sb + TH_LO + a_loff + ka);
#pragma unroll
            for (int t = 0; t < 8; t++) {
                uint32_t bo = b_loff + (uint32_t)(t * 16 * SPITCH * 2) + ka;
                uint32_t bh[4], bl[4];
                ldsm4(bh, sb + CH_HI + bo);
                ldsm4(bl, sb + CH_LO + bo);
                mma_bf16(fa[2 * t],     ah, bh[0], bh[1]);
                mma_bf16(fa[2 * t + 1], ah, bh[2], bh[3]);
                mma_bf16(fa[2 * t],     ah, bl[0], bl[1]);
                mma_bf16(fa[2 * t + 1], ah, bl[2], bl[3]);
                mma_bf16(fa[2 * t],     al, bh[0], bh[1]);
                mma_bf16(fa[2 * t + 1], al, bh[2], bh[3]);
            }
        }
        __syncthreads();   // all warps done reading CH (phi)

        // ---- P = exp(f) in registers; split to packed bf16 hi/lo; row-sum ----
        uint32_t pAh[16], pBh[16], pAl[16], pBl[16];
#pragma unroll
        for (int t = 0; t < 16; t++) {
            float e0 = __expf(fa[t][0]);
            float e1 = __expf(fa[t][1]);
            float e2 = __expf(fa[t][2]);
            float e3 = __expf(fa[t][3]);
            s0 += e0 + e1;
            s1 += e2 + e3;
            split2(e0, e1, pAh[t], pAl[t]);
            split2(e2, e3, pBh[t], pBl[t]);
        }

        // ---- load g chunk [c][k=m] split -> CH ----
        {
            const float* src = d_g + (size_t)b * C_INT * MSP + m0;
            for (int it = 0; it < 32; it++) {
                int lin = tid + it * 256;
                int row = lin >> 6;                 // c 0..127
                int c2  = (lin & 63) * 2;           // m offset
                float2 v = *(const float2*)(src + (size_t)row * MSP + c2);
                uint32_t hi, lo; split2(v.x, v.y, hi, lo);
                uint32_t off = (uint32_t)(row * (SPITCH * 2) + c2 * 2);
                *(uint32_t*)(smem + CH_HI + off) = hi;
                *(uint32_t*)(smem + CH_LO + off) = lo;
            }
        }
        __syncthreads();

        // ---- MMA2: y[16 x 128] += P x g^T (A from registers) ----
#pragma unroll
        for (int k8 = 0; k8 < 8; k8++) {
            uint32_t ka = (uint32_t)(k8 * 32);
            uint32_t ah[4] = {pAh[2 * k8], pBh[2 * k8], pAh[2 * k8 + 1], pBh[2 * k8 + 1]};
            uint32_t al[4] = {pAl[2 * k8], pBl[2 * k8], pAl[2 * k8 + 1], pBl[2 * k8 + 1]};
#pragma unroll
            for (int t = 0; t < 8; t++) {
                uint32_t bo = b_loff + (uint32_t)(t * 16 * SPITCH * 2) + ka;
                uint32_t bh[4], bl[4];
                ldsm4(bh, sb + CH_HI + bo);
                ldsm4(bl, sb + CH_LO + bo);
                mma_bf16(ya[2 * t],     ah, bh[0], bh[1]);
                mma_bf16(ya[2 * t + 1], ah, bh[2], bh[3]);
                mma_bf16(ya[2 * t],     ah, bl[0], bl[1]);
                mma_bf16(ya[2 * t + 1], ah, bl[2], bl[3]);
                mma_bf16(ya[2 * t],     al, bh[0], bh[1]);
                mma_bf16(ya[2 * t + 1], al, bh[2], bh[3]);
            }
        }
        __syncthreads();   // CH free for next chunk's phi
    }

    // ---- normalize by row sums (reduce across quad) and store ----
    s0 += __shfl_xor_sync(0xffffffffu, s0, 1);
    s0 += __shfl_xor_sync(0xffffffffu, s0, 2);
    s1 += __shfl_xor_sync(0xffffffffu, s1, 1);
    s1 += __shfl_xor_sync(0xffffffffu, s1, 2);
    float inv0 = 1.f / s0, inv1 = 1.f / s1;
    {
        int nrow0 = n0 + wn0 + g;
        float* dst0 = d_y + ((size_t)b * NSP + nrow0) * C_INT;
        float* dst1 = d_y + ((size_t)b * NSP + nrow0 + 8) * C_INT;
#pragma unroll
        for (int t = 0; t < 16; t++) {
            int ci = t * 8 + tig * 2;
            *(float2*)(dst0 + ci) = make_float2(ya[t][0] * inv0, ya[t][1] * inv0);
            *(float2*)(dst1 + ci) = make_float2(ya[t][2] * inv1, ya[t][3] * inv1);
        }
    }
}

// ---------------- zero BN stats ----------------
__global__ void zero_stats_kernel() {
    int t = threadIdx.x;
    if (t < 256) { d_sum[t] = 0.f; d_sumsq[t] = 0.f; }
}

// ---------------- W conv (GEMM 256x4096, K=128) + per-channel sum/sumsq --------------
__global__ __launch_bounds__(256) void wconv_kernel(const float* __restrict__ Ww,
                                                    const float* __restrict__ Wb) {
    __shared__ __align__(16) float As[16 * 64];
    __shared__ __align__(16) float Bs[16 * 128];
    int b  = blockIdx.z;
    int by = blockIdx.y;
    int bx = blockIdx.x;
    int c0 = by * 64;
    int n0 = bx * 128;
    int tid = threadIdx.x;
    int ty = tid >> 5;
    int tx = tid & 31;

    float acc[8][4];
#pragma unroll
    for (int i = 0; i < 8; i++)
#pragma unroll
        for (int j = 0; j < 4; j++) acc[i][j] = 0.f;

    int a_r = tid >> 2, a_k = (tid & 3) * 4;
    int b_n = tid >> 1, b_kq = (tid & 1) * 8;
    const float* yb = d_y + (size_t)b * NSP * C_INT;

    for (int k0 = 0; k0 < 128; k0 += 16) {
        float4 av = *(const float4*)&Ww[(c0 + a_r) * 128 + k0 + a_k];
        As[(a_k + 0) * 64 + a_r] = av.x;
        As[(a_k + 1) * 64 + a_r] = av.y;
        As[(a_k + 2) * 64 + a_r] = av.z;
        As[(a_k + 3) * 64 + a_r] = av.w;
#pragma unroll
        for (int h = 0; h < 2; h++) {
            float4 bv = *(const float4*)&yb[(size_t)(n0 + b_n) * C_INT + k0 + b_kq + h * 4];
            Bs[(b_kq + h * 4 + 0) * 128 + b_n] = bv.x;
            Bs[(b_kq + h * 4 + 1) * 128 + b_n] = bv.y;
            Bs[(b_kq + h * 4 + 2) * 128 + b_n] = bv.z;
            Bs[(b_kq + h * 4 + 3) * 128 + b_n] = bv.w;
        }
        __syncthreads();
#pragma unroll
        for (int kk = 0; kk < 16; kk++) {
            float4 a01 = *(const float4*)&As[kk * 64 + ty * 8];
            float4 a23 = *(const float4*)&As[kk * 64 + ty * 8 + 4];
            float a[8] = {a01.x, a01.y, a01.z, a01.w, a23.x, a23.y, a23.z, a23.w};
            float4 bv = *(const float4*)&Bs[kk * 128 + tx * 4];
#pragma unroll
            for (int i = 0; i < 8; i++) {
                acc[i][0] += a[i] * bv.x;
                acc[i][1] += a[i] * bv.y;
                acc[i][2] += a[i] * bv.z;
                acc[i][3] += a[i] * bv.w;
            }
        }
        __syncthreads();
    }

#pragma unroll
    for (int i = 0; i < 8; i++) {
        float bb = Wb[c0 + ty * 8 + i];
#pragma unroll
        for (int j = 0; j < 4; j++) acc[i][j] += bb;
        *(float4*)&d_Wy[((size_t)b * C_IN + c0 + ty * 8 + i) * NSP + n0 + tx * 4] =
            make_float4(acc[i][0], acc[i][1], acc[i][2], acc[i][3]);
    }

#pragma unroll
    for (int i = 0; i < 8; i++) {
        float s = acc[i][0] + acc[i][1] + acc[i][2] + acc[i][3];
        float q = acc[i][0] * acc[i][0] + acc[i][1] * acc[i][1]
                + acc[i][2] * acc[i][2] + acc[i][3] * acc[i][3];
#pragma unroll
        for (int o = 16; o; o >>= 1) {
            s += __shfl_xor_sync(0xffffffffu, s, o);
            q += __shfl_xor_sync(0xffffffffu, q, o);
        }
        if (tx == 0) {
            atomicAdd(&d_sum[c0 + ty * 8 + i], s);
            atomicAdd(&d_sumsq[c0 + ty * 8 + i], q);
        }
    }
}

// ---------------- BN (training stats) + residual ----------------
__global__ __launch_bounds__(256) void finalize_kernel(const float* __restrict__ x,
                                                       const float* __restrict__ gamma,
                                                       const float* __restrict__ beta,
                                                       float* __restrict__ out) {
    size_t i4  = (size_t)blockIdx.x * 256 + threadIdx.x;
    size_t idx = i4 * 4;
    int c = (int)((idx >> 12) & 255);
    float mean = d_sum[c] * (1.f / (float)NPIX);
    float var  = d_sumsq[c] * (1.f / (float)NPIX) - mean * mean;
    float inv  = 1.f / sqrtf(fmaxf(var, 0.f) + 1e-5f);
    float ga = gamma[c] * inv;
    float be = beta[c] - mean * ga;
    float4 w  = *(const float4*)&d_Wy[idx];
    float4 xv = *(const float4*)&x[idx];
    float4 o;
    o.x = w.x * ga + be + xv.x;
    o.y = w.y * ga + be + xv.y;
    o.z = w.z * ga + be + xv.z;
    o.w = w.w * ga + be + xv.w;
    *(float4*)&out[idx] = o;
}

// ---------------- launcher ----------------
extern "C" void kernel_launch(void* const* d_in, const int* in_sizes, int n_in,
                              void* d_out, int out_size) {
    const float* x       = (const float*)d_in[0];
    const float* theta_w = (const float*)d_in[1];
    const float* theta_b = (const float*)d_in[2];
    const float* phi_w   = (const float*)d_in[3];
    const float* phi_b   = (const float*)d_in[4];
    const float* g_w     = (const float*)d_in[5];
    const float* g_b     = (const float*)d_in[6];
    const float* W_w     = (const float*)d_in[7];
    const float* W_b     = (const float*)d_in[8];
    const float* bn_g    = (const float*)d_in[9];
    const float* bn_b    = (const float*)d_in[10];
    float* out = (float*)d_out;

    cudaFuncSetAttribute(attn_tc_kernel, cudaFuncAttributeMaxDynamicSharedMemorySize, ATTN_SMEM);

    pack_kernel<<<384, 256>>>(theta_w, theta_b, phi_w, phi_b, g_w, g_b);
    conv3_kernel<<<dim3(32, 6, BATCH), 256>>>(x);
    attn_tc_kernel<<<dim3(32, BATCH), 256, ATTN_SMEM>>>();
    zero_stats_kernel<<<1, 256>>>();
    wconv_kernel<<<dim3(32, 4, BATCH), 256>>>(W_w, W_b);
    finalize_kernel<<<8192, 256>>>(x, bn_g, bn_b, out);
}

// round 10
// speedup vs baseline: 1.8118x; 1.0602x over previous
#include <cuda_runtime.h>
#include <cuda_bf16.h>
#include <stdint.h>
#include <cstdint>
#include <math.h>

#define BATCH 8
#define C_IN 256
#define C_INT 128
#define NSP 4096   // H*W = 64*64
#define MSP 1024   // pooled spatial = 32*32
#define NPIX 32768 // BATCH*NSP

// ---------------- scratch (static device arrays; no allocation) ----------------
__device__ float d_theta[BATCH * C_INT * NSP];   // [B][Ci][N]   16 MB
__device__ float d_phi  [BATCH * MSP * C_INT];   // [B][M][Ci]    4 MB  (row m, k=ci contiguous)
__device__ float d_g    [BATCH * C_INT * MSP];   // [B][Ci][M]    4 MB  (row c, k=m contiguous)
__device__ float d_y    [BATCH * NSP * C_INT];   // [B][N][Ci]   16 MB
__device__ float d_Wy   [BATCH * C_IN * NSP];    // [B][C][N]    32 MB
__device__ float d_wpack[384 * C_IN];
__device__ float d_bpack[384];
__device__ float d_sum  [C_IN];
__device__ float d_sumsq[C_IN];

// ======================= warp-MMA helpers (sm_80+, safe on sm_103) =======================
__device__ __forceinline__ uint32_t smem_u32(const void* p) {
    uint32_t a;
    asm("{ .reg .u64 t; cvta.to.shared.u64 t, %1; cvt.u32.u64 %0, t; }" : "=r"(a) : "l"(p));
    return a;
}
__device__ __forceinline__ void ldsm4(uint32_t* r, uint32_t addr) {
    asm volatile("ldmatrix.sync.aligned.m8n8.x4.shared.b16 {%0,%1,%2,%3}, [%4];"
        : "=r"(r[0]), "=r"(r[1]), "=r"(r[2]), "=r"(r[3]) : "r"(addr));
}
__device__ __forceinline__ void mma_bf16(float* c, const uint32_t* a, uint32_t b0, uint32_t b1) {
    asm volatile("mma.sync.aligned.m16n8k16.row.col.f32.bf16.bf16.f32 "
        "{%0,%1,%2,%3}, {%4,%5,%6,%7}, {%8,%9}, {%0,%1,%2,%3};"
        : "+f"(c[0]), "+f"(c[1]), "+f"(c[2]), "+f"(c[3])
        : "r"(a[0]), "r"(a[1]), "r"(a[2]), "r"(a[3]), "r"(b0), "r"(b1));
}
// split fp32 pair into packed bf16x2 hi + lo(residual)
__device__ __forceinline__ void split2(float v0, float v1, uint32_t& hi, uint32_t& lo) {
    __nv_bfloat16 h0 = __float2bfloat16(v0), h1 = __float2bfloat16(v1);
    float r0 = v0 - __bfloat162float(h0), r1 = v1 - __bfloat162float(h1);
    __nv_bfloat16 l0 = __float2bfloat16(r0), l1 = __float2bfloat16(r1);
    hi = (uint32_t)__bfloat16_as_ushort(h0) | ((uint32_t)__bfloat16_as_ushort(h1) << 16);
    lo = (uint32_t)__bfloat16_as_ushort(l0) | ((uint32_t)__bfloat16_as_ushort(l1) << 16);
}

// SMEM layout: bf16 tiles, 128 rows x 128 cols, row pitch 136 bf16 (= 272 B)
#define SPITCH 136
#define TH_HI 0
#define TH_LO 34816
#define CH_HI 69632
#define CH_LO 104448
#define ATTN_SMEM 139264

// ---------------- pack theta/phi/g weights into one [384,256] matrix ----------------
__global__ void pack_kernel(const float* __restrict__ tw, const float* __restrict__ tb,
                            const float* __restrict__ pw, const float* __restrict__ pb,
                            const float* __restrict__ gw, const float* __restrict__ gb) {
    int row = blockIdx.x;
    int t = threadIdx.x;
    const float* w; const float* bs; int r;
    if (row < 128)      { w = tw; bs = tb; r = row; }
    else if (row < 256) { w = pw; bs = pb; r = row - 128; }
    else                { w = gw; bs = gb; r = row - 256; }
    d_wpack[row * 256 + t] = w[r * 256 + t];
    if (t == 0) d_bpack[row] = bs[r];
}

// ---------------- conv3 on tensor cores: C[384,4096] = Wpack x X, pool fused ----------
// grid (32 n-tiles, 3 m-tiles, 8 batch), 256 threads (8 warps), warp = 16 m-rows.
__global__ __launch_bounds__(256, 1) void conv3_tc_kernel(const float* __restrict__ x) {
    extern __shared__ __align__(16) char smem[];
    uint32_t sb = smem_u32(smem);
    int tid  = threadIdx.x;
    int wid  = tid >> 5;
    int lane = tid & 31;
    int b  = blockIdx.z;
    int by = blockIdx.y;                 // 0 theta, 1 phi, 2 g
    int bx = blockIdx.x;
    int row0 = by * 128;
    int n0   = bx * 128;
    int wn0 = wid * 16;
    int g   = lane >> 2;
    int tig = lane & 3;
    int within = lane & 7, sub = lane >> 3;
    uint32_t a_loff = (uint32_t)((wn0 + (sub & 1) * 8 + within) * (SPITCH * 2) + (sub >> 1) * 16);
    uint32_t b_loff = (uint32_t)(((sub >> 1) * 8 + within) * (SPITCH * 2) + (sub & 1) * 16);

    float ya[16][4];
#pragma unroll
    for (int t = 0; t < 16; t++)
#pragma unroll
        for (int j = 0; j < 4; j++) ya[t][j] = 0.f;

    const float* xb = x + (size_t)b * C_IN * NSP;

    for (int kc = 0; kc < 2; kc++) {
        int k0 = kc * 128;
        // ---- stage A: wpack[row0+r][k0..k0+127] split hi/lo (k-contiguous, no transpose) ----
        for (int it = 0; it < 32; it++) {
            int lin = tid + it * 256;          // 0..8191 float2
            int r   = lin >> 6;                // 0..127
            int k2  = (lin & 63) * 2;          // 0..126
            float2 v = *(const float2*)&d_wpack[(row0 + r) * 256 + k0 + k2];
            uint32_t hi, lo; split2(v.x, v.y, hi, lo);
            uint32_t off = (uint32_t)(r * (SPITCH * 2) + k2 * 2);
            *(uint32_t*)(smem + TH_HI + off) = hi;
            *(uint32_t*)(smem + TH_LO + off) = lo;
        }
        // ---- stage B: x[k][n] -> smem[n][k] split hi/lo (transpose on store) ----
        for (int it = 0; it < 32; it++) {
            int lin = tid + it * 256;          // 0..8191
            int k   = lin >> 6;                // 0..127
            int n2  = (lin & 63) * 2;          // 0..126
            const float* src = xb + (size_t)(k0 + k) * NSP + n0 + n2;
            float v0 = src[0], v1 = src[1];
            __nv_bfloat16 h0 = __float2bfloat16(v0), h1 = __float2bfloat16(v1);
            float r0 = v0 - __bfloat162float(h0), r1 = v1 - __bfloat162float(h1);
            __nv_bfloat16* bh = (__nv_bfloat16*)(smem + CH_HI);
            __nv_bfloat16* bl = (__nv_bfloat16*)(smem + CH_LO);
            bh[n2 * SPITCH + k] = h0;
            bh[(n2 + 1) * SPITCH + k] = h1;
            bl[n2 * SPITCH + k] = __float2bfloat16(r0);
            bl[(n2 + 1) * SPITCH + k] = __float2bfloat16(r1);
        }
        __syncthreads();

#pragma unroll
        for (int k8 = 0; k8 < 8; k8++) {
            uint32_t ka = (uint32_t)(k8 * 32);
            uint32_t ah[4], al[4];
            ldsm4(ah, sb + TH_HI + a_loff + ka);
            ldsm4(al, sb + TH_LO + a_loff + ka);
#pragma unroll
            for (int t = 0; t < 8; t++) {
                uint32_t bo = b_loff + (uint32_t)(t * 16 * SPITCH * 2) + ka;
                uint32_t bh[4], bl[4];
                ldsm4(bh, sb + CH_HI + bo);
                ldsm4(bl, sb + CH_LO + bo);
                mma_bf16(ya[2 * t],     ah, bh[0], bh[1]);
                mma_bf16(ya[2 * t + 1], ah, bh[2], bh[3]);
                mma_bf16(ya[2 * t],     ah, bl[0], bl[1]);
                mma_bf16(ya[2 * t + 1], ah, bl[2], bl[3]);
                mma_bf16(ya[2 * t],     al, bh[0], bh[1]);
                mma_bf16(ya[2 * t + 1], al, bh[2], bh[3]);
            }
        }
        __syncthreads();
    }

    // ---- epilogue: bias, then theta-write or fused 2x2 maxpool ----
    float b0 = d_bpack[row0 + wn0 + g];
    float b1 = d_bpack[row0 + wn0 + g + 8];
#pragma unroll
    for (int t = 0; t < 16; t++) {
        ya[t][0] += b0; ya[t][1] += b0;
        ya[t][2] += b1; ya[t][3] += b1;
    }

    if (by == 0) {
        int ci0 = wn0 + g, ci1 = wn0 + g + 8;
        float* dst0 = d_theta + ((size_t)b * C_INT + ci0) * NSP + n0;
        float* dst1 = d_theta + ((size_t)b * C_INT + ci1) * NSP + n0;
#pragma unroll
        for (int t = 0; t < 16; t++) {
            int c = t * 8 + tig * 2;
            *(float2*)(dst0 + c) = make_float2(ya[t][0], ya[t][1]);
            *(float2*)(dst1 + c) = make_float2(ya[t][2], ya[t][3]);
        }
    } else {
        // pooling: cols (c, c+1) in fragment t; cols (c+64, c+65) in fragment t+8
        int ci0 = wn0 + g, ci1 = wn0 + g + 8;
#pragma unroll
        for (int t = 0; t < 8; t++) {
            float p0 = fmaxf(fmaxf(ya[t][0], ya[t][1]), fmaxf(ya[t + 8][0], ya[t + 8][1]));
            float p1 = fmaxf(fmaxf(ya[t][2], ya[t][3]), fmaxf(ya[t + 8][2], ya[t + 8][3]));
            int m = bx * 32 + t * 4 + tig;
            if (by == 1) {
                d_phi[((size_t)b * MSP + m) * C_INT + ci0] = p0;
                d_phi[((size_t)b * MSP + m) * C_INT + ci1] = p1;
            } else {
                d_g[((size_t)b * C_INT + ci0) * MSP + m] = p0;
                d_g[((size_t)b * C_INT + ci1) * MSP + m] = p1;
            }
        }
    }
}

// ---------------- attention via mma.sync bf16x3 (flash, P kept in registers) ----------
// grid (32, 8), 256 threads (8 warps); block = 128 n-rows. Warp w owns rows 16w..16w+15.
__global__ __launch_bounds__(256, 1) void attn_tc_kernel() {
    extern __shared__ __align__(16) char smem[];
    uint32_t sb = smem_u32(smem);
    int tid  = threadIdx.x;
    int wid  = tid >> 5;
    int lane = tid & 31;
    int b  = blockIdx.y;
    int n0 = blockIdx.x * 128;
    int wn0 = wid * 16;
    int g   = lane >> 2;
    int tig = lane & 3;

    int within = lane & 7, sub = lane >> 3;
    uint32_t a_loff = (uint32_t)((wn0 + (sub & 1) * 8 + within) * (SPITCH * 2) + (sub >> 1) * 16);
    uint32_t b_loff = (uint32_t)(((sub >> 1) * 8 + within) * (SPITCH * 2) + (sub & 1) * 16);

    // ---- stage theta tile [n][k=ci] split hi/lo into smem ----
    {
        const float* tp = d_theta + (size_t)b * C_INT * NSP + n0;
        for (int it = 0; it < 32; it++) {
            int lin = tid + it * 256;
            int ci  = lin >> 6;
            int n2  = (lin & 63) * 2;
            float v0 = tp[(size_t)ci * NSP + n2];
            float v1 = tp[(size_t)ci * NSP + n2 + 1];
            __nv_bfloat16 h0 = __float2bfloat16(v0), h1 = __float2bfloat16(v1);
            float r0 = v0 - __bfloat162float(h0), r1 = v1 - __bfloat162float(h1);
            __nv_bfloat16* th = (__nv_bfloat16*)(smem + TH_HI);
            __nv_bfloat16* tl = (__nv_bfloat16*)(smem + TH_LO);
            th[n2 * SPITCH + ci] = h0;
            th[(n2 + 1) * SPITCH + ci] = h1;
            tl[n2 * SPITCH + ci] = __float2bfloat16(r0);
            tl[(n2 + 1) * SPITCH + ci] = __float2bfloat16(r1);
        }
    }
    __syncthreads();

    float ya[16][4];
#pragma unroll
    for (int t = 0; t < 16; t++)
#pragma unroll
        for (int j = 0; j < 4; j++) ya[t][j] = 0.f;
    float s0 = 0.f, s1 = 0.f;

    for (int mc = 0; mc < 8; mc++) {
        int m0 = mc * 128;
        // ---- load phi chunk [m][k=ci] split -> CH ----
        {
            const float* src = d_phi + ((size_t)b * MSP + m0) * C_INT;
            for (int it = 0; it < 32; it++) {
                int lin = tid + it * 256;
                int row = lin >> 6;
                int c2  = (lin & 63) * 2;
                float2 v = *(const float2*)(src + (size_t)row * C_INT + c2);
                uint32_t hi, lo; split2(v.x, v.y, hi, lo);
                uint32_t off = (uint32_t)(row * (SPITCH * 2) + c2 * 2);
                *(uint32_t*)(smem + CH_HI + off) = hi;
                *(uint32_t*)(smem + CH_LO + off) = lo;
            }
        }
        __syncthreads();

        // ---- MMA1: f[16 x 128] = theta x phi^T (bf16x3) ----
        float fa[16][4];
#pragma unroll
        for (int t = 0; t < 16; t++)
#pragma unroll
            for (int j = 0; j < 4; j++) fa[t][j] = 0.f;
#pragma unroll
        for (int k8 = 0; k8 < 8; k8++) {
            uint32_t ka = (uint32_t)(k8 * 32);
            uint32_t ah[4], al[4];
            ldsm4(ah, sb + TH_HI + a_loff + ka);
            ldsm4(al, sb + TH_LO + a_loff + ka);
#pragma unroll
            for (int t = 0; t < 8; t++) {
                uint32_t bo = b_loff + (uint32_t)(t * 16 * SPITCH * 2) + ka;
                uint32_t bh[4], bl[4];
                ldsm4(bh, sb + CH_HI + bo);
                ldsm4(bl, sb + CH_LO + bo);
                mma_bf16(fa[2 * t],     ah, bh[0], bh[1]);
                mma_bf16(fa[2 * t + 1], ah, bh[2], bh[3]);
                mma_bf16(fa[2 * t],     ah, bl[0], bl[1]);
                mma_bf16(fa[2 * t + 1], ah, bl[2], bl[3]);
                mma_bf16(fa[2 * t],     al, bh[0], bh[1]);
                mma_bf16(fa[2 * t + 1], al, bh[2], bh[3]);
            }
        }
        __syncthreads();

        // ---- P = exp(f) in registers; split packed; row-sum ----
        uint32_t pAh[16], pBh[16], pAl[16], pBl[16];
#pragma unroll
        for (int t = 0; t < 16; t++) {
            float e0 = __expf(fa[t][0]);
            float e1 = __expf(fa[t][1]);
            float e2 = __expf(fa[t][2]);
            float e3 = __expf(fa[t][3]);
            s0 += e0 + e1;
            s1 += e2 + e3;
            split2(e0, e1, pAh[t], pAl[t]);
            split2(e2, e3, pBh[t], pBl[t]);
        }

        // ---- load g chunk [c][k=m] split -> CH ----
        {
            const float* src = d_g + (size_t)b * C_INT * MSP + m0;
            for (int it = 0; it < 32; it++) {
                int lin = tid + it * 256;
                int row = lin >> 6;
                int c2  = (lin & 63) * 2;
                float2 v = *(const float2*)(src + (size_t)row * MSP + c2);
                uint32_t hi, lo; split2(v.x, v.y, hi, lo);
                uint32_t off = (uint32_t)(row * (SPITCH * 2) + c2 * 2);
                *(uint32_t*)(smem + CH_HI + off) = hi;
                *(uint32_t*)(smem + CH_LO + off) = lo;
            }
        }
        __syncthreads();

        // ---- MMA2: y[16 x 128] += P x g^T (A from registers) ----
#pragma unroll
        for (int k8 = 0; k8 < 8; k8++) {
            uint32_t ka = (uint32_t)(k8 * 32);
            uint32_t ah[4] = {pAh[2 * k8], pBh[2 * k8], pAh[2 * k8 + 1], pBh[2 * k8 + 1]};
            uint32_t al[4] = {pAl[2 * k8], pBl[2 * k8], pAl[2 * k8 + 1], pBl[2 * k8 + 1]};
#pragma unroll
            for (int t = 0; t < 8; t++) {
                uint32_t bo = b_loff + (uint32_t)(t * 16 * SPITCH * 2) + ka;
                uint32_t bh[4], bl[4];
                ldsm4(bh, sb + CH_HI + bo);
                ldsm4(bl, sb + CH_LO + bo);
                mma_bf16(ya[2 * t],     ah, bh[0], bh[1]);
                mma_bf16(ya[2 * t + 1], ah, bh[2], bh[3]);
                mma_bf16(ya[2 * t],     ah, bl[0], bl[1]);
                mma_bf16(ya[2 * t + 1], ah, bl[2], bl[3]);
                mma_bf16(ya[2 * t],     al, bh[0], bh[1]);
                mma_bf16(ya[2 * t + 1], al, bh[2], bh[3]);
            }
        }
        __syncthreads();
    }

    // ---- normalize by row sums (reduce across quad) and store ----
    s0 += __shfl_xor_sync(0xffffffffu, s0, 1);
    s0 += __shfl_xor_sync(0xffffffffu, s0, 2);
    s1 += __shfl_xor_sync(0xffffffffu, s1, 1);
    s1 += __shfl_xor_sync(0xffffffffu, s1, 2);
    float inv0 = 1.f / s0, inv1 = 1.f / s1;
    {
        int nrow0 = n0 + wn0 + g;
        float* dst0 = d_y + ((size_t)b * NSP + nrow0) * C_INT;
        float* dst1 = d_y + ((size_t)b * NSP + nrow0 + 8) * C_INT;
#pragma unroll
        for (int t = 0; t < 16; t++) {
            int ci = t * 8 + tig * 2;
            *(float2*)(dst0 + ci) = make_float2(ya[t][0] * inv0, ya[t][1] * inv0);
            *(float2*)(dst1 + ci) = make_float2(ya[t][2] * inv1, ya[t][3] * inv1);
        }
    }
}

// ---------------- zero BN stats ----------------
__global__ void zero_stats_kernel() {
    int t = threadIdx.x;
    if (t < 256) { d_sum[t] = 0.f; d_sumsq[t] = 0.f; }
}

// ---------------- W conv on tensor cores: C[256,4096] = Ww x y^T, BN stats fused ------
// grid (32, 2, 8), 256 threads; warp = 16 c-rows, K=128 single chunk.
__global__ __launch_bounds__(256, 1) void wconv_tc_kernel(const float* __restrict__ Ww,
                                                          const float* __restrict__ Wb) {
    extern __shared__ __align__(16) char smem[];
    uint32_t sb = smem_u32(smem);
    int tid  = threadIdx.x;
    int wid  = tid >> 5;
    int lane = tid & 31;
    int b  = blockIdx.z;
    int c0 = blockIdx.y * 128;
    int n0 = blockIdx.x * 128;
    int wn0 = wid * 16;
    int g   = lane >> 2;
    int tig = lane & 3;
    int within = lane & 7, sub = lane >> 3;
    uint32_t a_loff = (uint32_t)((wn0 + (sub & 1) * 8 + within) * (SPITCH * 2) + (sub >> 1) * 16);
    uint32_t b_loff = (uint32_t)(((sub >> 1) * 8 + within) * (SPITCH * 2) + (sub & 1) * 16);

    // ---- stage A: Ww[c0+r][k] split (k-contiguous) ----
    for (int it = 0; it < 32; it++) {
        int lin = tid + it * 256;
        int r   = lin >> 6;
        int k2  = (lin & 63) * 2;
        float2 v = *(const float2*)&Ww[(c0 + r) * 128 + k2];
        uint32_t hi, lo; split2(v.x, v.y, hi, lo);
        uint32_t off = (uint32_t)(r * (SPITCH * 2) + k2 * 2);
        *(uint32_t*)(smem + TH_HI + off) = hi;
        *(uint32_t*)(smem + TH_LO + off) = lo;
    }
    // ---- stage B: y[n][ci] split (already k-contiguous, no transpose) ----
    {
        const float* src = d_y + ((size_t)b * NSP + n0) * C_INT;
        for (int it = 0; it < 32; it++) {
            int lin = tid + it * 256;
            int r   = lin >> 6;
            int k2  = (lin & 63) * 2;
            float2 v = *(const float2*)(src + (size_t)r * C_INT + k2);
            uint32_t hi, lo; split2(v.x, v.y, hi, lo);
            uint32_t off = (uint32_t)(r * (SPITCH * 2) + k2 * 2);
            *(uint32_t*)(smem + CH_HI + off) = hi;
            *(uint32_t*)(smem + CH_LO + off) = lo;
        }
    }
    __syncthreads();

    float ya[16][4];
#pragma unroll
    for (int t = 0; t < 16; t++)
#pragma unroll
        for (int j = 0; j < 4; j++) ya[t][j] = 0.f;

#pragma unroll
    for (int k8 = 0; k8 < 8; k8++) {
        uint32_t ka = (uint32_t)(k8 * 32);
        uint32_t ah[4], al[4];
        ldsm4(ah, sb + TH_HI + a_loff + ka);
        ldsm4(al, sb + TH_LO + a_loff + ka);
#pragma unroll
        for (int t = 0; t < 8; t++) {
            uint32_t bo = b_loff + (uint32_t)(t * 16 * SPITCH * 2) + ka;
            uint32_t bh[4], bl[4];
            ldsm4(bh, sb + CH_HI + bo);
            ldsm4(bl, sb + CH_LO + bo);
            mma_bf16(ya[2 * t],     ah, bh[0], bh[1]);
            mma_bf16(ya[2 * t + 1], ah, bh[2], bh[3]);
            mma_bf16(ya[2 * t],     ah, bl[0], bl[1]);
            mma_bf16(ya[2 * t + 1], ah, bl[2], bl[3]);
            mma_bf16(ya[2 * t],     al, bh[0], bh[1]);
            mma_bf16(ya[2 * t + 1], al, bh[2], bh[3]);
        }
    }

    // ---- epilogue: bias, write Wy, per-channel sum/sumsq ----
    int c0g = c0 + wn0 + g;
    float b0 = Wb[c0g], b1 = Wb[c0g + 8];
    float s0 = 0.f, q0 = 0.f, s1 = 0.f, q1 = 0.f;
    float* dst0 = d_Wy + ((size_t)b * C_IN + c0g) * NSP + n0;
    float* dst1 = d_Wy + ((size_t)b * C_IN + c0g + 8) * NSP + n0;
#pragma unroll
    for (int t = 0; t < 16; t++) {
        float v0 = ya[t][0] + b0, v1 = ya[t][1] + b0;
        float v2 = ya[t][2] + b1, v3 = ya[t][3] + b1;
        int c = t * 8 + tig * 2;
        *(float2*)(dst0 + c) = make_float2(v0, v1);
        *(float2*)(dst1 + c) = make_float2(v2, v3);
        s0 += v0 + v1; q0 += v0 * v0 + v1 * v1;
        s1 += v2 + v3; q1 += v2 * v2 + v3 * v3;
    }
    s0 += __shfl_xor_sync(0xffffffffu, s0, 1);
    s0 += __shfl_xor_sync(0xffffffffu, s0, 2);
    q0 += __shfl_xor_sync(0xffffffffu, q0, 1);
    q0 += __shfl_xor_sync(0xffffffffu, q0, 2);
    s1 += __shfl_xor_sync(0xffffffffu, s1, 1);
    s1 += __shfl_xor_sync(0xffffffffu, s1, 2);
    q1 += __shfl_xor_sync(0xffffffffu, q1, 1);
    q1 += __shfl_xor_sync(0xffffffffu, q1, 2);
    if (tig == 0) {
        atomicAdd(&d_sum[c0g], s0);
        atomicAdd(&d_sumsq[c0g], q0);
        atomicAdd(&d_sum[c0g + 8], s1);
        atomicAdd(&d_sumsq[c0g + 8], q1);
    }
}

// ---------------- BN (training stats) + residual ----------------
__global__ __launch_bounds__(256) void finalize_kernel(const float* __restrict__ x,
                                                       const float* __restrict__ gamma,
                                                       const float* __restrict__ beta,
                                                       float* __restrict__ out) {
    size_t i4  = (size_t)blockIdx.x * 256 + threadIdx.x;
    size_t idx = i4 * 4;
    int c = (int)((idx >> 12) & 255);
    float mean = d_sum[c] * (1.f / (float)NPIX);
    float var  = d_sumsq[c] * (1.f / (float)NPIX) - mean * mean;
    float inv  = 1.f / sqrtf(fmaxf(var, 0.f) + 1e-5f);
    float ga = gamma[c] * inv;
    float be = beta[c] - mean * ga;
    float4 w  = *(const float4*)&d_Wy[idx];
    float4 xv = *(const float4*)&x[idx];
    float4 o;
    o.x = w.x * ga + be + xv.x;
    o.y = w.y * ga + be + xv.y;
    o.z = w.z * ga + be + xv.z;
    o.w = w.w * ga + be + xv.w;
    *(float4*)&out[idx] = o;
}

// ---------------- launcher ----------------
extern "C" void kernel_launch(void* const* d_in, const int* in_sizes, int n_in,
                              void* d_out, int out_size) {
    const float* x       = (const float*)d_in[0];
    const float* theta_w = (const float*)d_in[1];
    const float* theta_b = (const float*)d_in[2];
    const float* phi_w   = (const float*)d_in[3];
    const float* phi_b   = (const float*)d_in[4];
    const float* g_w     = (const float*)d_in[5];
    const float* g_b     = (const float*)d_in[6];
    const float* W_w     = (const float*)d_in[7];
    const float* W_b     = (const float*)d_in[8];
    const float* bn_g    = (const float*)d_in[9];
    const float* bn_b    = (const float*)d_in[10];
    float* out = (float*)d_out;

    cudaFuncSetAttribute(attn_tc_kernel, cudaFuncAttributeMaxDynamicSharedMemorySize, ATTN_SMEM);
    cudaFuncSetAttribute(conv3_tc_kernel, cudaFuncAttributeMaxDynamicSharedMemorySize, ATTN_SMEM);
    cudaFuncSetAttribute(wconv_tc_kernel, cudaFuncAttributeMaxDynamicSharedMemorySize, ATTN_SMEM);

    pack_kernel<<<384, 256>>>(theta_w, theta_b, phi_w, phi_b, g_w, g_b);
    conv3_tc_kernel<<<dim3(32, 3, BATCH), 256, ATTN_SMEM>>>(x);
    attn_tc_kernel<<<dim3(32, BATCH), 256, ATTN_SMEM>>>();
    zero_stats_kernel<<<1, 256>>>();
    wconv_tc_kernel<<<dim3(32, 2, BATCH), 256, ATTN_SMEM>>>(W_w, W_b);
    finalize_kernel<<<8192, 256>>>(x, bn_g, bn_b, out);
}

// round 11
// speedup vs baseline: 2.8780x; 1.5885x over previous
#include <cuda_runtime.h>
#include <cuda_bf16.h>
#include <stdint.h>
#include <cstdint>
#include <math.h>

#define BATCH 8
#define C_IN 256
#define C_INT 128
#define NSP 4096   // H*W = 64*64
#define MSP 1024   // pooled spatial = 32*32
#define NPIX 32768 // BATCH*NSP

// ---------------- scratch (static device arrays; no allocation) ----------------
__device__ float d_theta[BATCH * C_INT * NSP];                      // [B][Ci][N] fp32
__device__ __align__(16) __nv_bfloat16 d_phi_h[BATCH * MSP * C_INT];   // [B][M][Ci]
__device__ __align__(16) __nv_bfloat16 d_phi_l[BATCH * MSP * C_INT];
__device__ __align__(16) __nv_bfloat16 d_g_h[BATCH * C_INT * MSP];     // [B][Ci][M]
__device__ __align__(16) __nv_bfloat16 d_g_l[BATCH * C_INT * MSP];
__device__ __align__(16) __nv_bfloat16 d_y_h[BATCH * NSP * C_INT];     // [B][N][Ci]
__device__ __align__(16) __nv_bfloat16 d_y_l[BATCH * NSP * C_INT];
__device__ float d_Wy[BATCH * C_IN * NSP];                          // [B][C][N]
__device__ __align__(16) __nv_bfloat16 d_wp_h[384 * C_IN];             // packed conv weights
__device__ __align__(16) __nv_bfloat16 d_wp_l[384 * C_IN];
__device__ __align__(16) __nv_bfloat16 d_wW_h[C_IN * C_INT];           // W conv weights
__device__ __align__(16) __nv_bfloat16 d_wW_l[C_IN * C_INT];
__device__ float d_bpack[384];
__device__ float d_sum  [C_IN];
__device__ float d_sumsq[C_IN];

// ======================= warp-MMA helpers (sm_80+, safe on sm_103) =======================
__device__ __forceinline__ uint32_t smem_u32(const void* p) {
    uint32_t a;
    asm("{ .reg .u64 t; cvta.to.shared.u64 t, %1; cvt.u32.u64 %0, t; }" : "=r"(a) : "l"(p));
    return a;
}
__device__ __forceinline__ void ldsm4(uint32_t* r, uint32_t addr) {
    asm volatile("ldmatrix.sync.aligned.m8n8.x4.shared.b16 {%0,%1,%2,%3}, [%4];"
        : "=r"(r[0]), "=r"(r[1]), "=r"(r[2]), "=r"(r[3]) : "r"(addr));
}
__device__ __forceinline__ void mma_bf16(float* c, const uint32_t* a, uint32_t b0, uint32_t b1) {
    asm volatile("mma.sync.aligned.m16n8k16.row.col.f32.bf16.bf16.f32 "
        "{%0,%1,%2,%3}, {%4,%5,%6,%7}, {%8,%9}, {%0,%1,%2,%3};"
        : "+f"(c[0]), "+f"(c[1]), "+f"(c[2]), "+f"(c[3])
        : "r"(a[0]), "r"(a[1]), "r"(a[2]), "r"(a[3]), "r"(b0), "r"(b1));
}
__device__ __forceinline__ void split2(float v0, float v1, uint32_t& hi, uint32_t& lo) {
    __nv_bfloat16 h0 = __float2bfloat16(v0), h1 = __float2bfloat16(v1);
    float r0 = v0 - __bfloat162float(h0), r1 = v1 - __bfloat162float(h1);
    __nv_bfloat16 l0 = __float2bfloat16(r0), l1 = __float2bfloat16(r1);
    hi = (uint32_t)__bfloat16_as_ushort(h0) | ((uint32_t)__bfloat16_as_ushort(h1) << 16);
    lo = (uint32_t)__bfloat16_as_ushort(l0) | ((uint32_t)__bfloat16_as_ushort(l1) << 16);
}

// SMEM tile: 128 rows x 128 bf16, pitch 136 bf16 (272 B). Tile = 34816 B.
#define SPITCH 136
#define TILE_B 34816
// attention / wconv smem
#define TH_HI 0
#define TH_LO 34816
#define CH_HI 69632
#define CH_LO 104448
#define ATTN_SMEM 139264
// conv3 smem (A + two X chunks, all split)
#define C3_A_HI 0
#define C3_A_LO 34816
#define C3_X_HI(kc) (69632 + (kc) * 69632)
#define C3_X_LO(kc) (104448 + (kc) * 69632)
#define C3_SMEM 208896

// ---------------- pack theta/phi/g weights into split bf16 [384,256] ----------------
__global__ void pack_kernel(const float* __restrict__ tw, const float* __restrict__ tb,
                            const float* __restrict__ pw, const float* __restrict__ pb,
                            const float* __restrict__ gw, const float* __restrict__ gb) {
    int row = blockIdx.x;
    int t = threadIdx.x;
    const float* w; const float* bs; int r;
    if (row < 128)      { w = tw; bs = tb; r = row; }
    else if (row < 256) { w = pw; bs = pb; r = row - 128; }
    else                { w = gw; bs = gb; r = row - 256; }
    float v = w[r * 256 + t];
    __nv_bfloat16 h = __float2bfloat16(v);
    d_wp_h[row * 256 + t] = h;
    d_wp_l[row * 256 + t] = __float2bfloat16(v - __bfloat162float(h));
    if (t == 0) d_bpack[row] = bs[r];
}

// ---------------- split W conv weights [256,128] ----------------
__global__ void wsplit_kernel(const float* __restrict__ Ww) {
    int idx = blockIdx.x * 256 + threadIdx.x;   // 0..32767
    float v = Ww[idx];
    __nv_bfloat16 h = __float2bfloat16(v);
    d_wW_h[idx] = h;
    d_wW_l[idx] = __float2bfloat16(v - __bfloat162float(h));
}

// ---------------- conv3 on tensor cores; x staged ONCE per tile; pool fused ----------
// grid (32 n-tiles, 8 batch), 256 threads (8 warps).
__global__ __launch_bounds__(256, 1) void conv3_tc_kernel(const float* __restrict__ x) {
    extern __shared__ __align__(16) char smem[];
    uint32_t sb = smem_u32(smem);
    int tid  = threadIdx.x;
    int wid  = tid >> 5;
    int lane = tid & 31;
    int b  = blockIdx.y;
    int bx = blockIdx.x;
    int n0 = bx * 128;
    int wn0 = wid * 16;
    int g   = lane >> 2;
    int tig = lane & 3;
    int within = lane & 7, sub = lane >> 3;
    uint32_t a_loff = (uint32_t)((wn0 + (sub & 1) * 8 + within) * (SPITCH * 2) + (sub >> 1) * 16);
    uint32_t b_loff = (uint32_t)(((sub >> 1) * 8 + within) * (SPITCH * 2) + (sub & 1) * 16);

    const float* xb = x + (size_t)b * C_IN * NSP;

    // ---- stage BOTH x chunks: [k][n] -> smem [n][k] split hi/lo (transpose, once) ----
#pragma unroll
    for (int kc = 0; kc < 2; kc++) {
        int k0 = kc * 128;
        char* xh = smem + C3_X_HI(kc);
        char* xl = smem + C3_X_LO(kc);
        for (int it = 0; it < 32; it++) {
            int lin = tid + it * 256;
            int k   = lin >> 6;
            int n2  = (lin & 63) * 2;
            const float* src = xb + (size_t)(k0 + k) * NSP + n0 + n2;
            float v0 = src[0], v1 = src[1];
            __nv_bfloat16 h0 = __float2bfloat16(v0), h1 = __float2bfloat16(v1);
            float r0 = v0 - __bfloat162float(h0), r1 = v1 - __bfloat162float(h1);
            ((__nv_bfloat16*)xh)[n2 * SPITCH + k] = h0;
            ((__nv_bfloat16*)xh)[(n2 + 1) * SPITCH + k] = h1;
            ((__nv_bfloat16*)xl)[n2 * SPITCH + k] = __float2bfloat16(r0);
            ((__nv_bfloat16*)xl)[(n2 + 1) * SPITCH + k] = __float2bfloat16(r1);
        }
    }

    for (int by = 0; by < 3; by++) {
        float ya[16][4];
#pragma unroll
        for (int t = 0; t < 16; t++)
#pragma unroll
            for (int j = 0; j < 4; j++) ya[t][j] = 0.f;

        for (int kc = 0; kc < 2; kc++) {
            __syncthreads();   // protect A overwrite (and X visibility on first pass)
            // ---- stage A: copy pre-split wpack rows [by*128, +128), k-chunk kc ----
            {
                const uint4* srcH = (const uint4*)(d_wp_h + (size_t)(by * 128) * 256 + kc * 128);
                const uint4* srcL = (const uint4*)(d_wp_l + (size_t)(by * 128) * 256 + kc * 128);
#pragma unroll
                for (int it = 0; it < 8; it++) {
                    int lin = tid + it * 256;       // 0..2047
                    int row = lin >> 4, v = lin & 15;
                    // gmem row pitch = 256 bf16 = 32 uint4
                    *(uint4*)(smem + C3_A_HI + row * (SPITCH * 2) + v * 16) = srcH[row * 32 + v];
                    *(uint4*)(smem + C3_A_LO + row * (SPITCH * 2) + v * 16) = srcL[row * 32 + v];
                }
            }
            __syncthreads();

            uint32_t xh_base = sb + C3_X_HI(kc), xl_base = sb + C3_X_LO(kc);
#pragma unroll
            for (int k8 = 0; k8 < 8; k8++) {
                uint32_t ka = (uint32_t)(k8 * 32);
                uint32_t ah[4], al[4];
                ldsm4(ah, sb + C3_A_HI + a_loff + ka);
                ldsm4(al, sb + C3_A_LO + a_loff + ka);
#pragma unroll
                for (int t = 0; t < 8; t++) {
                    uint32_t bo = b_loff + (uint32_t)(t * 16 * SPITCH * 2) + ka;
                    uint32_t bh[4], bl[4];
                    ldsm4(bh, xh_base + bo);
                    ldsm4(bl, xl_base + bo);
                    mma_bf16(ya[2 * t],     ah, bh[0], bh[1]);
                    mma_bf16(ya[2 * t + 1], ah, bh[2], bh[3]);
                    mma_bf16(ya[2 * t],     ah, bl[0], bl[1]);
                    mma_bf16(ya[2 * t + 1], ah, bl[2], bl[3]);
                    mma_bf16(ya[2 * t],     al, bh[0], bh[1]);
                    mma_bf16(ya[2 * t + 1], al, bh[2], bh[3]);
                }
            }
        }

        // ---- epilogue ----
        int row0 = by * 128;
        float b0 = d_bpack[row0 + wn0 + g];
        float b1 = d_bpack[row0 + wn0 + g + 8];
#pragma unroll
        for (int t = 0; t < 16; t++) {
            ya[t][0] += b0; ya[t][1] += b0;
            ya[t][2] += b1; ya[t][3] += b1;
        }
        int ci0 = wn0 + g, ci1 = wn0 + g + 8;

        if (by == 0) {
            float* dst0 = d_theta + ((size_t)b * C_INT + ci0) * NSP + n0;
            float* dst1 = d_theta + ((size_t)b * C_INT + ci1) * NSP + n0;
#pragma unroll
            for (int t = 0; t < 16; t++) {
                int c = t * 8 + tig * 2;
                *(float2*)(dst0 + c) = make_float2(ya[t][0], ya[t][1]);
                *(float2*)(dst1 + c) = make_float2(ya[t][2], ya[t][3]);
            }
        } else {
            // 2x2 maxpool fully fragment-local, then split-store bf16 hi/lo
#pragma unroll
            for (int t = 0; t < 8; t++) {
                float p0 = fmaxf(fmaxf(ya[t][0], ya[t][1]), fmaxf(ya[t + 8][0], ya[t + 8][1]));
                float p1 = fmaxf(fmaxf(ya[t][2], ya[t][3]), fmaxf(ya[t + 8][2], ya[t + 8][3]));
                int m = bx * 32 + t * 4 + tig;
                __nv_bfloat16 h0 = __float2bfloat16(p0);
                __nv_bfloat16 l0 = __float2bfloat16(p0 - __bfloat162float(h0));
                __nv_bfloat16 h1 = __float2bfloat16(p1);
                __nv_bfloat16 l1 = __float2bfloat16(p1 - __bfloat162float(h1));
                if (by == 1) {
                    size_t base = ((size_t)b * MSP + m) * C_INT;
                    d_phi_h[base + ci0] = h0; d_phi_l[base + ci0] = l0;
                    d_phi_h[base + ci1] = h1; d_phi_l[base + ci1] = l1;
                } else {
                    size_t base0 = ((size_t)b * C_INT + ci0) * MSP + m;
                    size_t base1 = ((size_t)b * C_INT + ci1) * MSP + m;
                    d_g_h[base0] = h0; d_g_l[base0] = l0;
                    d_g_h[base1] = h1; d_g_l[base1] = l1;
                }
            }
        }
    }
}

// ---------------- attention via mma.sync bf16x3 (flash, P in registers) ----------
// grid (32, 8), 256 threads (8 warps); block = 128 n-rows.
__global__ __launch_bounds__(256, 1) void attn_tc_kernel() {
    extern __shared__ __align__(16) char smem[];
    uint32_t sb = smem_u32(smem);
    int tid  = threadIdx.x;
    int wid  = tid >> 5;
    int lane = tid & 31;
    int b  = blockIdx.y;
    int n0 = blockIdx.x * 128;
    int wn0 = wid * 16;
    int g   = lane >> 2;
    int tig = lane & 3;
    int within = lane & 7, sub = lane >> 3;
    uint32_t a_loff = (uint32_t)((wn0 + (sub & 1) * 8 + within) * (SPITCH * 2) + (sub >> 1) * 16);
    uint32_t b_loff = (uint32_t)(((sub >> 1) * 8 + within) * (SPITCH * 2) + (sub & 1) * 16);

    // ---- stage theta tile [n][k=ci] split hi/lo (transpose from fp32; once per block) ----
    {
        const float* tp = d_theta + (size_t)b * C_INT * NSP + n0;
        for (int it = 0; it < 32; it++) {
            int lin = tid + it * 256;
            int ci  = lin >> 6;
            int n2  = (lin & 63) * 2;
            float v0 = tp[(size_t)ci * NSP + n2];
            float v1 = tp[(size_t)ci * NSP + n2 + 1];
            __nv_bfloat16 h0 = __float2bfloat16(v0), h1 = __float2bfloat16(v1);
            float r0 = v0 - __bfloat162float(h0), r1 = v1 - __bfloat162float(h1);
            __nv_bfloat16* th = (__nv_bfloat16*)(smem + TH_HI);
            __nv_bfloat16* tl = (__nv_bfloat16*)(smem + TH_LO);
            th[n2 * SPITCH + ci] = h0;
            th[(n2 + 1) * SPITCH + ci] = h1;
            tl[n2 * SPITCH + ci] = __float2bfloat16(r0);
            tl[(n2 + 1) * SPITCH + ci] = __float2bfloat16(r1);
        }
    }
    __syncthreads();

    float ya[16][4];
#pragma unroll
    for (int t = 0; t < 16; t++)
#pragma unroll
        for (int j = 0; j < 4; j++) ya[t][j] = 0.f;
    float s0 = 0.f, s1 = 0.f;

    for (int mc = 0; mc < 8; mc++) {
        int m0 = mc * 128;
        // ---- stage phi chunk: pure uint4 copy of pre-split bf16 ----
        {
            const uint4* srcH = (const uint4*)(d_phi_h + ((size_t)b * MSP + m0) * C_INT);
            const uint4* srcL = (const uint4*)(d_phi_l + ((size_t)b * MSP + m0) * C_INT);
#pragma unroll
            for (int it = 0; it < 8; it++) {
                int lin = tid + it * 256;
                int row = lin >> 4, v = lin & 15;
                *(uint4*)(smem + CH_HI + row * (SPITCH * 2) + v * 16) = srcH[row * 16 + v];
                *(uint4*)(smem + CH_LO + row * (SPITCH * 2) + v * 16) = srcL[row * 16 + v];
            }
        }
        __syncthreads();

        // ---- MMA1: f[16 x 128] = theta x phi^T (bf16x3) ----
        float fa[16][4];
#pragma unroll
        for (int t = 0; t < 16; t++)
#pragma unroll
            for (int j = 0; j < 4; j++) fa[t][j] = 0.f;
#pragma unroll
        for (int k8 = 0; k8 < 8; k8++) {
            uint32_t ka = (uint32_t)(k8 * 32);
            uint32_t ah[4], al[4];
            ldsm4(ah, sb + TH_HI + a_loff + ka);
            ldsm4(al, sb + TH_LO + a_loff + ka);
#pragma unroll
            for (int t = 0; t < 8; t++) {
                uint32_t bo = b_loff + (uint32_t)(t * 16 * SPITCH * 2) + ka;
                uint32_t bh[4], bl[4];
                ldsm4(bh, sb + CH_HI + bo);
                ldsm4(bl, sb + CH_LO + bo);
                mma_bf16(fa[2 * t],     ah, bh[0], bh[1]);
                mma_bf16(fa[2 * t + 1], ah, bh[2], bh[3]);
                mma_bf16(fa[2 * t],     ah, bl[0], bl[1]);
                mma_bf16(fa[2 * t + 1], ah, bl[2], bl[3]);
                mma_bf16(fa[2 * t],     al, bh[0], bh[1]);
                mma_bf16(fa[2 * t + 1], al, bh[2], bh[3]);
            }
        }
        __syncthreads();

        // ---- P = exp(f) in registers; split packed; row-sum ----
        uint32_t pAh[16], pBh[16], pAl[16], pBl[16];
#pragma unroll
        for (int t = 0; t < 16; t++) {
            float e0 = __expf(fa[t][0]);
            float e1 = __expf(fa[t][1]);
            float e2 = __expf(fa[t][2]);
            float e3 = __expf(fa[t][3]);
            s0 += e0 + e1;
            s1 += e2 + e3;
            split2(e0, e1, pAh[t], pAl[t]);
            split2(e2, e3, pBh[t], pBl[t]);
        }

        // ---- stage g chunk: pure uint4 copy ----
        {
#pragma unroll
            for (int it = 0; it < 8; it++) {
                int lin = tid + it * 256;
                int row = lin >> 4, v = lin & 15;
                const __nv_bfloat16* sh = d_g_h + ((size_t)b * C_INT + row) * MSP + m0 + v * 8;
                const __nv_bfloat16* sl = d_g_l + ((size_t)b * C_INT + row) * MSP + m0 + v * 8;
                *(uint4*)(smem + CH_HI + row * (SPITCH * 2) + v * 16) = *(const uint4*)sh;
                *(uint4*)(smem + CH_LO + row * (SPITCH * 2) + v * 16) = *(const uint4*)sl;
            }
        }
        __syncthreads();

        // ---- MMA2: y[16 x 128] += P x g^T (A from registers) ----
#pragma unroll
        for (int k8 = 0; k8 < 8; k8++) {
            uint32_t ka = (uint32_t)(k8 * 32);
            uint32_t ah[4] = {pAh[2 * k8], pBh[2 * k8], pAh[2 * k8 + 1], pBh[2 * k8 + 1]};
            uint32_t al[4] = {pAl[2 * k8], pBl[2 * k8], pAl[2 * k8 + 1], pBl[2 * k8 + 1]};
#pragma unroll
            for (int t = 0; t < 8; t++) {
                uint32_t bo = b_loff + (uint32_t)(t * 16 * SPITCH * 2) + ka;
                uint32_t bh[4], bl[4];
                ldsm4(bh, sb + CH_HI + bo);
                ldsm4(bl, sb + CH_LO + bo);
                mma_bf16(ya[2 * t],     ah, bh[0], bh[1]);
                mma_bf16(ya[2 * t + 1], ah, bh[2], bh[3]);
                mma_bf16(ya[2 * t],     ah, bl[0], bl[1]);
                mma_bf16(ya[2 * t + 1], ah, bl[2], bl[3]);
                mma_bf16(ya[2 * t],     al, bh[0], bh[1]);
                mma_bf16(ya[2 * t + 1], al, bh[2], bh[3]);
            }
        }
        __syncthreads();
    }

    // ---- normalize by row sums; write y SPLIT bf16 [n][ci] ----
    s0 += __shfl_xor_sync(0xffffffffu, s0, 1);
    s0 += __shfl_xor_sync(0xffffffffu, s0, 2);
    s1 += __shfl_xor_sync(0xffffffffu, s1, 1);
    s1 += __shfl_xor_sync(0xffffffffu, s1, 2);
    float inv0 = 1.f / s0, inv1 = 1.f / s1;
    {
        int nrow0 = n0 + wn0 + g;
        size_t base0 = ((size_t)b * NSP + nrow0) * C_INT;
        size_t base1 = ((size_t)b * NSP + nrow0 + 8) * C_INT;
#pragma unroll
        for (int t = 0; t < 16; t++) {
            int ci = t * 8 + tig * 2;
            uint32_t h0, l0, h1, l1;
            split2(ya[t][0] * inv0, ya[t][1] * inv0, h0, l0);
            split2(ya[t][2] * inv1, ya[t][3] * inv1, h1, l1);
            *(uint32_t*)(d_y_h + base0 + ci) = h0;
            *(uint32_t*)(d_y_l + base0 + ci) = l0;
            *(uint32_t*)(d_y_h + base1 + ci) = h1;
            *(uint32_t*)(d_y_l + base1 + ci) = l1;
        }
    }
}

// ---------------- zero BN stats ----------------
__global__ void zero_stats_kernel() {
    int t = threadIdx.x;
    if (t < 256) { d_sum[t] = 0.f; d_sumsq[t] = 0.f; }
}

// ---------------- W conv on tensor cores; pre-split operands; BN stats fused ------
// grid (32, 2, 8), 256 threads; warp = 16 c-rows, K=128 single chunk.
__global__ __launch_bounds__(256, 1) void wconv_tc_kernel(const float* __restrict__ Wb) {
    extern __shared__ __align__(16) char smem[];
    uint32_t sb = smem_u32(smem);
    int tid  = threadIdx.x;
    int wid  = tid >> 5;
    int lane = tid & 31;
    int b  = blockIdx.z;
    int c0 = blockIdx.y * 128;
    int n0 = blockIdx.x * 128;
    int wn0 = wid * 16;
    int g   = lane >> 2;
    int tig = lane & 3;
    int within = lane & 7, sub = lane >> 3;
    uint32_t a_loff = (uint32_t)((wn0 + (sub & 1) * 8 + within) * (SPITCH * 2) + (sub >> 1) * 16);
    uint32_t b_loff = (uint32_t)(((sub >> 1) * 8 + within) * (SPITCH * 2) + (sub & 1) * 16);

    // ---- stage A (Ww rows c0..+128) and B (y rows n0..+128): pure uint4 copies ----
    {
        const uint4* aH = (const uint4*)(d_wW_h + (size_t)c0 * C_INT);
        const uint4* aL = (const uint4*)(d_wW_l + (size_t)c0 * C_INT);
        const uint4* bH = (const uint4*)(d_y_h + ((size_t)b * NSP + n0) * C_INT);
        const uint4* bL = (const uint4*)(d_y_l + ((size_t)b * NSP + n0) * C_INT);
#pragma unroll
        for (int it = 0; it < 8; it++) {
            int lin = tid + it * 256;
            int row = lin >> 4, v = lin & 15;
            uint32_t so = (uint32_t)(row * (SPITCH * 2) + v * 16);
            *(uint4*)(smem + TH_HI + so) = aH[row * 16 + v];
            *(uint4*)(smem + TH_LO + so) = aL[row * 16 + v];
            *(uint4*)(smem + CH_HI + so) = bH[row * 16 + v];
            *(uint4*)(smem + CH_LO + so) = bL[row * 16 + v];
        }
    }
    __syncthreads();

    float ya[16][4];
#pragma unroll
    for (int t = 0; t < 16; t++)
#pragma unroll
        for (int j = 0; j < 4; j++) ya[t][j] = 0.f;

#pragma unroll
    for (int k8 = 0; k8 < 8; k8++) {
        uint32_t ka = (uint32_t)(k8 * 32);
        uint32_t ah[4], al[4];
        ldsm4(ah, sb + TH_HI + a_loff + ka);
        ldsm4(al, sb + TH_LO + a_loff + ka);
#pragma unroll
        for (int t = 0; t < 8; t++) {
            uint32_t bo = b_loff + (uint32_t)(t * 16 * SPITCH * 2) + ka;
            uint32_t bh[4], bl[4];
            ldsm4(bh, sb + CH_HI + bo);
            ldsm4(bl, sb + CH_LO + bo);
            mma_bf16(ya[2 * t],     ah, bh[0], bh[1]);
            mma_bf16(ya[2 * t + 1], ah, bh[2], bh[3]);
            mma_bf16(ya[2 * t],     ah, bl[0], bl[1]);
            mma_bf16(ya[2 * t + 1], ah, bl[2], bl[3]);
            mma_bf16(ya[2 * t],     al, bh[0], bh[1]);
            mma_bf16(ya[2 * t + 1], al, bh[2], bh[3]);
        }
    }

    // ---- epilogue: bias, write Wy, per-channel sum/sumsq ----
    int c0g = c0 + wn0 + g;
    float b0 = Wb[c0g], b1 = Wb[c0g + 8];
    float s0 = 0.f, q0 = 0.f, s1 = 0.f, q1 = 0.f;
    float* dst0 = d_Wy + ((size_t)b * C_IN + c0g) * NSP + n0;
    float* dst1 = d_Wy + ((size_t)b * C_IN + c0g + 8) * NSP + n0;
#pragma unroll
    for (int t = 0; t < 16; t++) {
        float v0 = ya[t][0] + b0, v1 = ya[t][1] + b0;
        float v2 = ya[t][2] + b1, v3 = ya[t][3] + b1;
        int c = t * 8 + tig * 2;
        *(float2*)(dst0 + c) = make_float2(v0, v1);
        *(float2*)(dst1 + c) = make_float2(v2, v3);
        s0 += v0 + v1; q0 += v0 * v0 + v1 * v1;
        s1 += v2 + v3; q1 += v2 * v2 + v3 * v3;
    }
    s0 += __shfl_xor_sync(0xffffffffu, s0, 1);
    s0 += __shfl_xor_sync(0xffffffffu, s0, 2);
    q0 += __shfl_xor_sync(0xffffffffu, q0, 1);
    q0 += __shfl_xor_sync(0xffffffffu, q0, 2);
    s1 += __shfl_xor_sync(0xffffffffu, s1, 1);
    s1 += __shfl_xor_sync(0xffffffffu, s1, 2);
    q1 += __shfl_xor_sync(0xffffffffu, q1, 1);
    q1 += __shfl_xor_sync(0xffffffffu, q1, 2);
    if (tig == 0) {
        atomicAdd(&d_sum[c0g], s0);
        atomicAdd(&d_sumsq[c0g], q0);
        atomicAdd(&d_sum[c0g + 8], s1);
        atomicAdd(&d_sumsq[c0g + 8], q1);
    }
}

// ---------------- BN (training stats) + residual ----------------
__global__ __launch_bounds__(256) void finalize_kernel(const float* __restrict__ x,
                                                       const float* __restrict__ gamma,
                                                       const float* __restrict__ beta,
                                                       float* __restrict__ out) {
    size_t i4  = (size_t)blockIdx.x * 256 + threadIdx.x;
    size_t idx = i4 * 4;
    int c = (int)((idx >> 12) & 255);
    float mean = d_sum[c] * (1.f / (float)NPIX);
    float var  = d_sumsq[c] * (1.f / (float)NPIX) - mean * mean;
    float inv  = 1.f / sqrtf(fmaxf(var, 0.f) + 1e-5f);
    float ga = gamma[c] * inv;
    float be = beta[c] - mean * ga;
    float4 w  = *(const float4*)&d_Wy[idx];
    float4 xv = *(const float4*)&x[idx];
    float4 o;
    o.x = w.x * ga + be + xv.x;
    o.y = w.y * ga + be + xv.y;
    o.z = w.z * ga + be + xv.z;
    o.w = w.w * ga + be + xv.w;
    *(float4*)&out[idx] = o;
}

// ---------------- launcher ----------------
extern "C" void kernel_launch(void* const* d_in, const int* in_sizes, int n_in,
                              void* d_out, int out_size) {
    const float* x       = (const float*)d_in[0];
    const float* theta_w = (const float*)d_in[1];
    const float* theta_b = (const float*)d_in[2];
    const float* phi_w   = (const float*)d_in[3];
    const float* phi_b   = (const float*)d_in[4];
    const float* g_w     = (const float*)d_in[5];
    const float* g_b     = (const float*)d_in[6];
    const float* W_w     = (const float*)d_in[7];
    const float* W_b     = (const float*)d_in[8];
    const float* bn_g    = (const float*)d_in[9];
    const float* bn_b    = (const float*)d_in[10];
    float* out = (float*)d_out;

    cudaFuncSetAttribute(attn_tc_kernel, cudaFuncAttributeMaxDynamicSharedMemorySize, ATTN_SMEM);
    cudaFuncSetAttribute(conv3_tc_kernel, cudaFuncAttributeMaxDynamicSharedMemorySize, C3_SMEM);
    cudaFuncSetAttribute(wconv_tc_kernel, cudaFuncAttributeMaxDynamicSharedMemorySize, ATTN_SMEM);

    pack_kernel<<<384, 256>>>(theta_w, theta_b, phi_w, phi_b, g_w, g_b);
    wsplit_kernel<<<128, 256>>>(W_w);
    conv3_tc_kernel<<<dim3(32, BATCH), 256, C3_SMEM>>>(x);
    attn_tc_kernel<<<dim3(32, BATCH), 256, ATTN_SMEM>>>();
    zero_stats_kernel<<<1, 256>>>();
    wconv_tc_kernel<<<dim3(32, 2, BATCH), 256, ATTN_SMEM>>>(W_b);
    finalize_kernel<<<8192, 256>>>(x, bn_g, bn_b, out);
}